// round 12
// baseline (speedup 1.0000x reference)
#include <cuda_runtime.h>

#define T_STEPS 1000
#define BATCH   4096
#define IN_SZ   8
#define HID     50
#define OUT_SZ  6
#define NT      64            // lanes = rows: 0..49 hid, 50..55 out, 56..63 x-producers
#define GB      4             // batch elements per block (share weight registers)
#define VW      64            // v width: [r(50) | x(8) | dead(6)]
#define NPAIR   30            // 60-col weight row = 30 f32x2 pairs
#define DT_F    0.1f

typedef unsigned long long ull;

__device__ __forceinline__ ull pack2(float lo, float hi) {
    ull u; asm("mov.b64 %0, {%1, %2};" : "=l"(u) : "f"(lo), "f"(hi)); return u;
}
__device__ __forceinline__ void unpack2(ull u, float& lo, float& hi) {
    asm("mov.b64 {%0, %1}, %2;" : "=f"(lo), "=f"(hi) : "l"(u));
}
#define FMA2(acc, a, b) asm("fma.rn.f32x2 %0, %1, %2, %0;" : "+l"(acc) : "l"(a), "l"(b))
#define ADD2(d, a, b)   asm("add.rn.f32x2 %0, %1, %2;" : "=l"(d) : "l"(a), "l"(b))

__global__ void __launch_bounds__(NT, 7) biornn_kernel(
    const float* __restrict__ x,      // (T, B, 8)
    const float* __restrict__ Win,    // (50, 8)
    const float* __restrict__ Wrec,   // (50, 50)
    const float* __restrict__ bias,   // (50,)
    const float* __restrict__ Wow,    // (6, 50)
    const float* __restrict__ Wob,    // (6,)
    float* __restrict__ out)          // (T, B, 6)
{
    __shared__ __align__(16) float v_s[2][GB][VW];   // 2 KB

    const int row = threadIdx.x;      // 0..63
    const int b0  = blockIdx.x * GB;

    const bool is_hid  = (row < HID);
    const bool is_out  = (row >= HID) && (row < HID + OUT_SZ);
    const bool is_prod = (row >= 56);

    for (int i = row; i < 2 * GB * VW; i += NT) ((float*)v_s)[i] = 0.f;

    // ---- 60-col weight row packed into 30 ull pairs (shared across all GB batches) ----
    ull wv[NPAIR];
    ull bjp;
    if (is_hid) {
        const float* wr = Wrec + row * HID;
#pragma unroll
        for (int i = 0; i < 25; i++) wv[i] = pack2(wr[2 * i], wr[2 * i + 1]);
        const float* wi = Win + row * IN_SZ;
#pragma unroll
        for (int i = 0; i < 4; i++) wv[25 + i] = pack2(wi[2 * i], wi[2 * i + 1]);
        wv[29] = 0ULL;                                   // cols 58,59
        bjp = pack2(bias[row], 0.f);
    } else if (is_out) {
        const float* wo = Wow + (row - HID) * HID;
#pragma unroll
        for (int i = 0; i < 25; i++) wv[i] = pack2(wo[2 * i], wo[2 * i + 1]);
#pragma unroll
        for (int i = 25; i < NPAIR; i++) wv[i] = 0ULL;
        bjp = pack2(Wob[row - HID], 0.f);
    } else {
#pragma unroll
        for (int i = 0; i < NPAIR; i++) wv[i] = 0ULL;
        bjp = 0ULL;
    }

    // ---- branchless 2-deep x pipeline for GB batches ----
    // producer lane 56+i owns x[t][b0+g][i]; batch offset g*IN_SZ is an immediate
    const int xi = is_prod ? (row - 56) : 0;
    const float* xptr = x + (size_t)b0 * IN_SZ + xi;
    const size_t XS = (size_t)BATCH * IN_SZ;
    float xA[GB], xB[GB];
#pragma unroll
    for (int g = 0; g < GB; g++) { xA[g] = xptr[g * IN_SZ]; xB[g] = xptr[XS + g * IN_SZ]; }
    xptr += 2 * XS;                                       // -> x_2

    // STS slot: hid -> row; prod -> 50+xi; out -> dead 58..63
    const int slot = is_hid ? row : (is_prod ? (row - 6) : (row + 8));

    // out pointer: batch g at immediate offset g*OUT_SZ
    float* op = out + (is_out ? ((size_t)b0 * OUT_SZ + (row - HID)) : 0);

    float*            sbA = &v_s[0][0][0];
    float*            sbB = &v_s[1][0][0];
    const ulonglong2* vpA = reinterpret_cast<const ulonglong2*>(&v_s[0][0][0]);
    const ulonglong2* vpB = reinterpret_cast<const ulonglong2*>(&v_s[1][0][0]);

    float h[GB];
#pragma unroll
    for (int g = 0; g < GB; g++) h[g] = 0.f;

    __syncthreads();

#pragma unroll 1
    for (int t = 0; t < T_STEPS; t++) {
        // publish v entries for all GB batches (branchless)
#pragma unroll
        for (int g = 0; g < GB; g++)
            sbA[g * VW + slot] = is_prod ? xA[g] : fmaxf(h[g], 0.f);

        __syncthreads();

        // advance x pipeline (pointer clamped near the end)
#pragma unroll
        for (int g = 0; g < GB; g++) { xA[g] = xB[g]; xB[g] = xptr[g * IN_SZ]; }
        if (t < T_STEPS - 3) xptr += XS;

        // GB independent dots: 15 broadcast LDS.128 + 30 FMA2 each, 2 chains/dot
        float s[GB];
#pragma unroll
        for (int g = 0; g < GB; g++) {
            const ulonglong2* vp = vpA + g * (VW / 4);
            ull a0 = bjp, a1 = 0ULL;
#pragma unroll
            for (int kk = 0; kk < 15; kk++) {
                const ulonglong2 v2 = vp[kk];
                FMA2(a0, wv[2 * kk],     v2.x);
                FMA2(a1, wv[2 * kk + 1], v2.y);
            }
            ADD2(a0, a0, a1);
            float sl, sh;
            unpack2(a0, sl, sh);
            s[g] = sl + sh;
        }

        if (is_out) {
#pragma unroll
            for (int g = 0; g < GB; g++) op[g * OUT_SZ] = s[g];
        }
        op += (size_t)BATCH * OUT_SZ;

#pragma unroll
        for (int g = 0; g < GB; g++) h[g] = fmaf(DT_F, s[g] - h[g], h[g]);

        // swap double buffers
        float* ts = sbA; sbA = sbB; sbB = ts;
        const ulonglong2* tv = vpA; vpA = vpB; vpB = tv;
    }
}

extern "C" void kernel_launch(void* const* d_in, const int* in_sizes, int n_in,
                              void* d_out, int out_size) {
    const float* x    = (const float*)d_in[0];
    const float* Win  = (const float*)d_in[1];
    const float* Wrec = (const float*)d_in[2];
    const float* bias = (const float*)d_in[3];
    const float* Wow  = (const float*)d_in[4];
    const float* Wob  = (const float*)d_in[5];
    float* out = (float*)d_out;

    biornn_kernel<<<BATCH / GB, NT>>>(x, Win, Wrec, bias, Wow, Wob, out);
}

// round 13
// speedup vs baseline: 2.0047x; 2.0047x over previous
#include <cuda_runtime.h>

#define T_STEPS 1000
#define BATCH   4096
#define IN_SZ   8
#define HID     50
#define OUT_SZ  6
#define NT      32            // ONE warp per block; lane owns rows {lane, lane+32}
#define GB      4             // batch elements per block (share weight regs)
#define VW      64            // v width: [r(50) | x(8) | dead(6)]
#define NPAIR   30            // 60-col weight row = 30 f32x2 pairs
#define DT_F    0.1f

typedef unsigned long long ull;

__device__ __forceinline__ ull pack2(float lo, float hi) {
    ull u; asm("mov.b64 %0, {%1, %2};" : "=l"(u) : "f"(lo), "f"(hi)); return u;
}
__device__ __forceinline__ void unpack2(ull u, float& lo, float& hi) {
    asm("mov.b64 {%0, %1}, %2;" : "=f"(lo), "=f"(hi) : "l"(u));
}
#define FMA2(acc, a, b) asm("fma.rn.f32x2 %0, %1, %2, %0;" : "+l"(acc) : "l"(a), "l"(b))
#define ADD2(d, a, b)   asm("add.rn.f32x2 %0, %1, %2;" : "=l"(d) : "l"(a), "l"(b))

__global__ void __launch_bounds__(NT, 8) biornn_kernel(   // 256-reg cap: spill-impossible
    const float* __restrict__ x,      // (T, B, 8)
    const float* __restrict__ Win,    // (50, 8)
    const float* __restrict__ Wrec,   // (50, 50)
    const float* __restrict__ bias,   // (50,)
    const float* __restrict__ Wow,    // (6, 50)
    const float* __restrict__ Wob,    // (6,)
    float* __restrict__ out)          // (T, B, 6)
{
    __shared__ __align__(16) float v_s[2][GB][VW];   // 2 KB

    const int lane = threadIdx.x;     // 0..31
    const int b0   = blockIdx.x * GB;

    // row0 = lane (always hidden); row1 = lane+32:
    //   lane<18  -> row1 32..49 hidden
    //   18..23   -> row1 50..55 output
    //   24..31   -> row1 56..63 dead -> x producer for x[b][lane-24]
    const bool r1_hid  = (lane < 18);
    const bool r1_out  = (lane >= 18) && (lane < 24);
    const bool is_prod = (lane >= 24);

    for (int i = lane; i < 2 * GB * VW; i += NT) ((float*)v_s)[i] = 0.f;

    // ---- two 60-col weight rows packed into 2x30 ull pairs ----
    ull w0[NPAIR], w1[NPAIR];
    ull bj0p, bj1p;
    {
        const float* wr = Wrec + lane * HID;           // row0 always hidden
#pragma unroll
        for (int i = 0; i < 25; i++) w0[i] = pack2(wr[2 * i], wr[2 * i + 1]);
        const float* wi = Win + lane * IN_SZ;
#pragma unroll
        for (int i = 0; i < 4; i++) w0[25 + i] = pack2(wi[2 * i], wi[2 * i + 1]);
        w0[29] = 0ULL;
        bj0p = pack2(bias[lane], 0.f);

        if (r1_hid) {
            const int r1 = lane + 32;
            const float* wr1 = Wrec + r1 * HID;
#pragma unroll
            for (int i = 0; i < 25; i++) w1[i] = pack2(wr1[2 * i], wr1[2 * i + 1]);
            const float* wi1 = Win + r1 * IN_SZ;
#pragma unroll
            for (int i = 0; i < 4; i++) w1[25 + i] = pack2(wi1[2 * i], wi1[2 * i + 1]);
            w1[29] = 0ULL;
            bj1p = pack2(bias[r1], 0.f);
        } else if (r1_out) {
            const float* wo = Wow + (lane - 18) * HID;
#pragma unroll
            for (int i = 0; i < 25; i++) w1[i] = pack2(wo[2 * i], wo[2 * i + 1]);
#pragma unroll
            for (int i = 25; i < NPAIR; i++) w1[i] = 0ULL;
            bj1p = pack2(Wob[lane - 18], 0.f);
        } else {
#pragma unroll
            for (int i = 0; i < NPAIR; i++) w1[i] = 0ULL;
            bj1p = 0ULL;
        }
    }

    // ---- branchless 2-deep x pipeline (producers: lanes 24..31) ----
    const int xi = is_prod ? (lane - 24) : 0;
    const float* xptr = x + (size_t)b0 * IN_SZ + xi;
    const size_t XS = (size_t)BATCH * IN_SZ;
    float xA[GB], xB[GB];
#pragma unroll
    for (int g = 0; g < GB; g++) { xA[g] = xptr[g * IN_SZ]; xB[g] = xptr[XS + g * IN_SZ]; }
    xptr += 2 * XS;

    // STS slots: slot0 = lane (rows 0..31). slot1: hidden -> lane+32;
    // out lanes -> dead 58..63; producers -> 50..57.
    const int slot1 = r1_hid ? (lane + 32) : (is_prod ? (lane + 26) : (lane + 40));

    float* op = out + (r1_out ? ((size_t)b0 * OUT_SZ + (lane - 18)) : 0);

    float*            sbA = &v_s[0][0][0];
    float*            sbB = &v_s[1][0][0];
    const ulonglong2* vpA = reinterpret_cast<const ulonglong2*>(&v_s[0][0][0]);
    const ulonglong2* vpB = reinterpret_cast<const ulonglong2*>(&v_s[1][0][0]);

    float h0[GB], h1[GB];
#pragma unroll
    for (int g = 0; g < GB; g++) { h0[g] = 0.f; h1[g] = 0.f; }

    __syncwarp();

#pragma unroll 1
    for (int t = 0; t < T_STEPS; t++) {
        // publish both v entries per batch (branchless; out lanes write dead slots)
#pragma unroll
        for (int g = 0; g < GB; g++) {
            sbA[g * VW + lane]  = fmaxf(h0[g], 0.f);
            sbA[g * VW + slot1] = is_prod ? xA[g] : fmaxf(h1[g], 0.f);
        }

        __syncwarp();

        // advance x pipeline (pointer clamped near the end)
#pragma unroll
        for (int g = 0; g < GB; g++) { xA[g] = xB[g]; xB[g] = xptr[g * IN_SZ]; }
        if (t < T_STEPS - 3) xptr += XS;

        // GB x 2 dots: 15 broadcast LDS.128 feed 60 FMA2 (4 chains) per batch
        float s0[GB], s1[GB];
#pragma unroll
        for (int g = 0; g < GB; g++) {
            const ulonglong2* vp = vpA + g * (VW / 4);
            ull p0 = bj0p, p1 = 0ULL, q0 = bj1p, q1 = 0ULL;
#pragma unroll
            for (int kk = 0; kk < 15; kk++) {
                const ulonglong2 v2 = vp[kk];
                FMA2(p0, w0[2 * kk],     v2.x);
                FMA2(p1, w0[2 * kk + 1], v2.y);
                FMA2(q0, w1[2 * kk],     v2.x);
                FMA2(q1, w1[2 * kk + 1], v2.y);
            }
            ADD2(p0, p0, p1);
            ADD2(q0, q0, q1);
            float al, ah, bl, bh;
            unpack2(p0, al, ah);  s0[g] = al + ah;
            unpack2(q0, bl, bh);  s1[g] = bl + bh;
        }

        if (r1_out) {
#pragma unroll
            for (int g = 0; g < GB; g++) op[g * OUT_SZ] = s1[g];
        }
        op += (size_t)BATCH * OUT_SZ;

#pragma unroll
        for (int g = 0; g < GB; g++) {
            h0[g] = fmaf(DT_F, s0[g] - h0[g], h0[g]);
            h1[g] = fmaf(DT_F, s1[g] - h1[g], h1[g]);   // garbage-but-finite for out/prod lanes
        }

        // swap double buffers
        float* ts = sbA; sbA = sbB; sbB = ts;
        const ulonglong2* tv = vpA; vpA = vpB; vpB = tv;
    }
}

extern "C" void kernel_launch(void* const* d_in, const int* in_sizes, int n_in,
                              void* d_out, int out_size) {
    const float* x    = (const float*)d_in[0];
    const float* Win  = (const float*)d_in[1];
    const float* Wrec = (const float*)d_in[2];
    const float* bias = (const float*)d_in[3];
    const float* Wow  = (const float*)d_in[4];
    const float* Wob  = (const float*)d_in[5];
    float* out = (float*)d_out;

    biornn_kernel<<<BATCH / GB, NT>>>(x, Win, Wrec, bias, Wow, Wob, out);
}